// round 1
// baseline (speedup 1.0000x reference)
#include <cuda_runtime.h>
#include <cuda_bf16.h>
#include <math.h>

// Problem constants (shapes fixed by the dataset)
#define NNODES 50000
#define NEDGES 800000
#define ETOT   (NEDGES + NNODES)   // self-loops appended

// ---------------- device scratch (static: no allocations allowed) -----------
__device__ float g_x[NNODES * 256];      // projected features [N, H*C]
__device__ float g_y[NNODES * 256];      // x folded through dense_w: [N, H, 64]
__device__ float g_asrc[NNODES * 4];     // per-node att logits (src)
__device__ float g_adst[NNODES * 4];     // per-node att logits (dst)
__device__ float g_denom[NNODES * 4];    // softmax denominators
__device__ float g_ex[ETOT * 4];         // exp(alpha) per edge per head
__device__ int   g_srcv[ETOT];
__device__ int   g_dstv[ETOT];
__device__ int   g_is64;                 // 1 if graph indices are int64

// ---------------- dtype detection for the edge index tensor -----------------
__global__ void k_detect(const int* __restrict__ g32) {
    __shared__ int any_nonzero;
    if (threadIdx.x == 0) any_nonzero = 0;
    __syncthreads();
    // If data is int64 (little-endian, values < 2^31), every odd 32-bit word is 0.
    int w = g32[2 * threadIdx.x + 1];
    if (w != 0) any_nonzero = 1;   // benign race: all writers store 1
    __syncthreads();
    if (threadIdx.x == 0) g_is64 = (any_nonzero == 0) ? 1 : 0;
}

// ---------------- init: out[n,d] = dense_b[d] + bias @ dense_w; denom = 0 ----
__global__ void k_init(const float* __restrict__ bias,
                       const float* __restrict__ dw,
                       const float* __restrict__ db,
                       float* __restrict__ out, int N) {
    __shared__ float b2[64];
    int t = threadIdx.x;
    if (t < 64) {
        float acc = db[t];
        #pragma unroll 8
        for (int k = 0; k < 256; k++) acc = fmaf(bias[k], dw[k * 64 + t], acc);
        b2[t] = acc;
    }
    __syncthreads();
    int total = N * 64;
    for (int i = blockIdx.x * blockDim.x + t; i < total; i += gridDim.x * blockDim.x)
        out[i] = b2[i & 63];
    int td = N * 4;
    for (int i = blockIdx.x * blockDim.x + t; i < td; i += gridDim.x * blockDim.x)
        g_denom[i] = 0.f;
}

// ---------------- x = emb @ W  ([N,64] @ [64,256]) --------------------------
// 256 threads: thread t owns output column t, W column held in 64 registers.
// 64 rows per block, staged 8 at a time in smem.
__global__ void __launch_bounds__(256) k_proj_x(const float* __restrict__ emb,
                                                const float* __restrict__ W, int N) {
    __shared__ float s_emb[8][64];
    int t = threadIdx.x;
    float w[64];
    #pragma unroll
    for (int k = 0; k < 64; k++) w[k] = W[k * 256 + t];

    int base = blockIdx.x * 64;
    for (int ch = 0; ch < 8; ch++) {
        int r0 = base + ch * 8;
        for (int i = t; i < 512; i += 256) {
            int rr = i >> 6, cc = i & 63;
            int row = r0 + rr;
            s_emb[rr][cc] = (row < N) ? emb[row * 64 + cc] : 0.f;
        }
        __syncthreads();
        #pragma unroll
        for (int r = 0; r < 8; r++) {
            int row = r0 + r;
            if (row < N) {
                float acc = 0.f;
                const float4* ep = (const float4*)s_emb[r];
                #pragma unroll
                for (int q = 0; q < 16; q++) {
                    float4 e4 = ep[q];
                    acc = fmaf(e4.x, w[4 * q + 0], acc);
                    acc = fmaf(e4.y, w[4 * q + 1], acc);
                    acc = fmaf(e4.z, w[4 * q + 2], acc);
                    acc = fmaf(e4.w, w[4 * q + 3], acc);
                }
                g_x[row * 256 + t] = acc;
            }
        }
        __syncthreads();
    }
}

// ---------------- per-node attention logits ---------------------------------
// one warp per node: a_src[n,h] = <x[n,h,:], att_src[h,:]>, same for dst.
__global__ void k_att(const float* __restrict__ asr,
                      const float* __restrict__ adt, int N) {
    int warp = (blockIdx.x * blockDim.x + threadIdx.x) >> 5;
    int lane = threadIdx.x & 31;
    if (warp >= N) return;
    const float* xr = &g_x[(size_t)warp * 256];
    #pragma unroll
    for (int h = 0; h < 4; h++) {
        float v1 = xr[h * 64 + lane], v2 = xr[h * 64 + 32 + lane];
        float a1 = asr[h * 64 + lane], a2 = asr[h * 64 + 32 + lane];
        float b1 = adt[h * 64 + lane], b2 = adt[h * 64 + 32 + lane];
        float ps = fmaf(v2, a2, v1 * a1);
        float pd = fmaf(v2, b2, v1 * b1);
        #pragma unroll
        for (int o = 16; o; o >>= 1) {
            ps += __shfl_xor_sync(0xffffffffu, ps, o);
            pd += __shfl_xor_sync(0xffffffffu, pd, o);
        }
        if (lane == 0) { g_asrc[warp * 4 + h] = ps; g_adst[warp * 4 + h] = pd; }
    }
}

// ---------------- y[n,h,d] = sum_c x[n,h,c] * dense_w[h*64+c, d] -------------
__global__ void __launch_bounds__(256) k_proj_y(const float* __restrict__ dw, int N) {
    __shared__ float s_x[8][256];
    int t = threadIdx.x;
    int h = t >> 6, d = t & 63;
    float wc[64];
    #pragma unroll
    for (int c = 0; c < 64; c++) wc[c] = dw[(h * 64 + c) * 64 + d];

    int base = blockIdx.x * 64;
    for (int ch = 0; ch < 8; ch++) {
        int r0 = base + ch * 8;
        for (int i = t; i < 8 * 256; i += 256) {
            int rr = i >> 8, cc = i & 255;
            int row = r0 + rr;
            s_x[rr][cc] = (row < N) ? g_x[row * 256 + cc] : 0.f;
        }
        __syncthreads();
        #pragma unroll
        for (int r = 0; r < 8; r++) {
            int row = r0 + r;
            if (row < N) {
                float acc = 0.f;
                const float4* xp = (const float4*)&s_x[r][h * 64];
                #pragma unroll
                for (int q = 0; q < 16; q++) {
                    float4 x4 = xp[q];
                    acc = fmaf(x4.x, wc[4 * q + 0], acc);
                    acc = fmaf(x4.y, wc[4 * q + 1], acc);
                    acc = fmaf(x4.z, wc[4 * q + 2], acc);
                    acc = fmaf(x4.w, wc[4 * q + 3], acc);
                }
                g_y[row * 256 + t] = acc;
            }
        }
        __syncthreads();
    }
}

// ---------------- edge pass 1: ex = exp(leaky(a)); denom += ex --------------
__global__ void k_edge(const void* __restrict__ graph, int E, int ET) {
    int e = blockIdx.x * blockDim.x + threadIdx.x;
    if (e >= ET) return;
    int s, d;
    if (e < E) {
        if (g_is64) {
            const long long* g = (const long long*)graph;
            s = (int)g[e]; d = (int)g[E + e];
        } else {
            const int* g = (const int*)graph;
            s = g[e]; d = g[E + e];
        }
    } else {
        s = d = e - E;   // self loop
    }
    g_srcv[e] = s; g_dstv[e] = d;

    float4 as4 = *(const float4*)&g_asrc[s * 4];
    float4 ad4 = *(const float4*)&g_adst[d * 4];
    float a0 = as4.x + ad4.x, a1 = as4.y + ad4.y, a2 = as4.z + ad4.z, a3 = as4.w + ad4.w;
    a0 = (a0 > 0.f) ? a0 : 0.2f * a0;
    a1 = (a1 > 0.f) ? a1 : 0.2f * a1;
    a2 = (a2 > 0.f) ? a2 : 0.2f * a2;
    a3 = (a3 > 0.f) ? a3 : 0.2f * a3;
    float4 ex4 = make_float4(expf(a0), expf(a1), expf(a2), expf(a3));
    *(float4*)&g_ex[e * 4] = ex4;

    float* dp = &g_denom[d * 4];
    asm volatile("red.global.v4.f32.add [%0], {%1, %2, %3, %4};"
                 :: "l"(dp), "f"(ex4.x), "f"(ex4.y), "f"(ex4.z), "f"(ex4.w)
                 : "memory");
}

// ---------------- edge pass 2: out[dst] += sum_h coef[h] * y[src,h,:] --------
// 16 lanes per edge, each lane handles 4 output dims via float4 + red.v4.
__global__ void __launch_bounds__(256) k_scatter(float* __restrict__ out, int ET) {
    int tid = blockIdx.x * blockDim.x + threadIdx.x;
    int e = tid >> 4;
    int l = tid & 15;
    if (e >= ET) return;
    int s = g_srcv[e], d = g_dstv[e];
    float4 ex4 = *(const float4*)&g_ex[e * 4];
    float4 dn  = *(const float4*)&g_denom[d * 4];
    float c0 = ex4.x / (dn.x + 1e-16f);
    float c1 = ex4.y / (dn.y + 1e-16f);
    float c2 = ex4.z / (dn.z + 1e-16f);
    float c3 = ex4.w / (dn.w + 1e-16f);

    const float4* yp = (const float4*)&g_y[(size_t)s * 256];
    float4 y0 = yp[0 * 16 + l];
    float4 y1 = yp[1 * 16 + l];
    float4 y2 = yp[2 * 16 + l];
    float4 y3 = yp[3 * 16 + l];

    float4 acc;
    acc.x = fmaf(c3, y3.x, fmaf(c2, y2.x, fmaf(c1, y1.x, c0 * y0.x)));
    acc.y = fmaf(c3, y3.y, fmaf(c2, y2.y, fmaf(c1, y1.y, c0 * y0.y)));
    acc.z = fmaf(c3, y3.z, fmaf(c2, y2.z, fmaf(c1, y1.z, c0 * y0.z)));
    acc.w = fmaf(c3, y3.w, fmaf(c2, y2.w, fmaf(c1, y1.w, c0 * y0.w)));

    float* op = out + (size_t)d * 64 + l * 4;
    asm volatile("red.global.v4.f32.add [%0], {%1, %2, %3, %4};"
                 :: "l"(op), "f"(acc.x), "f"(acc.y), "f"(acc.z), "f"(acc.w)
                 : "memory");
}

// ---------------- launch ------------------------------------------------------
extern "C" void kernel_launch(void* const* d_in, const int* in_sizes, int n_in,
                              void* d_out, int out_size) {
    const float* emb   = (const float*)d_in[0];
    const void*  graph = d_in[1];
    const float* W     = (const float*)d_in[2];
    const float* asr   = (const float*)d_in[3];
    const float* adt   = (const float*)d_in[4];
    const float* bias  = (const float*)d_in[5];
    const float* dw    = (const float*)d_in[6];
    const float* db    = (const float*)d_in[7];
    float* out = (float*)d_out;

    int N  = in_sizes[0] / 64;   // 50000
    int E  = in_sizes[1] / 2;    // 800000
    int ET = E + N;              // + self loops

    k_detect<<<1, 256>>>((const int*)graph);
    k_init<<<512, 256>>>(bias, dw, db, out, N);
    k_proj_x<<<(N + 63) / 64, 256>>>(emb, W, N);
    k_att<<<(N + 7) / 8, 256>>>(asr, adt, N);
    k_proj_y<<<(N + 63) / 64, 256>>>(dw, N);
    k_edge<<<(ET + 255) / 256, 256>>>(graph, E, ET);
    k_scatter<<<(ET + 15) / 16, 256>>>(out, ET);
}

// round 2
// speedup vs baseline: 1.4592x; 1.4592x over previous
#include <cuda_runtime.h>
#include <cuda_bf16.h>
#include <math.h>

#define NNODES 50000
#define NEDGES 800000
#define ETOT   (NEDGES + NNODES)

// ---------------- device scratch ----------------
__device__ float g_y[NNODES * 256];      // emb folded through W and dense_w: [N, H, 64]
__device__ float g_asrc[NNODES * 4];
__device__ float g_adst[NNODES * 4];
__device__ float g_denom[NNODES * 4];    // denom, then reciprocal after k_rdenom
__device__ float g_ex[ETOT * 4];
__device__ int2  g_sd[ETOT];             // packed (src, dst)
__device__ int   g_is64;
__device__ float g_wf[64 * 256];         // folded weights: emb -> y
__device__ float g_ws[64 * 4];           // emb -> a_src
__device__ float g_wd[64 * 4];           // emb -> a_dst

// ---------------- dtype detection of graph tensor ----------------
__global__ void k_detect(const int* __restrict__ g32) {
    __shared__ int any_nonzero;
    if (threadIdx.x == 0) any_nonzero = 0;
    __syncthreads();
    int w = g32[2 * threadIdx.x + 1];
    if (w != 0) any_nonzero = 1;
    __syncthreads();
    if (threadIdx.x == 0) g_is64 = (any_nonzero == 0) ? 1 : 0;
}

// ---------------- fold dense_w through W: Wfold[k, h*64+d] ----------------
// 256 blocks (one per output column j=(h,d)), 64 threads (one per k).
__global__ void __launch_bounds__(64) k_fold(const float* __restrict__ W,
                                             const float* __restrict__ dw) {
    int j = blockIdx.x;          // output column
    int h = j >> 6, d = j & 63;
    __shared__ float dcol[64];
    int k = threadIdx.x;
    dcol[k] = dw[(h * 64 + k) * 64 + d];
    __syncthreads();
    const float4* wr = (const float4*)&W[k * 256 + h * 64];
    float acc = 0.f;
    #pragma unroll
    for (int q = 0; q < 16; q++) {
        float4 w4 = wr[q];
        acc = fmaf(w4.x, dcol[4 * q + 0], acc);
        acc = fmaf(w4.y, dcol[4 * q + 1], acc);
        acc = fmaf(w4.z, dcol[4 * q + 2], acc);
        acc = fmaf(w4.w, dcol[4 * q + 3], acc);
    }
    g_wf[k * 256 + j] = acc;
}

// ---------------- fold att vectors through W: ws/wd [64,4] ----------------
// 8 blocks: b>>2 selects src/dst, b&3 = head. 64 threads (k).
__global__ void __launch_bounds__(64) k_fatt(const float* __restrict__ W,
                                             const float* __restrict__ asr,
                                             const float* __restrict__ adt) {
    int b = blockIdx.x;
    int sel = b >> 2, h = b & 3;
    __shared__ float av[64];
    int k = threadIdx.x;
    av[k] = sel ? adt[h * 64 + k] : asr[h * 64 + k];
    __syncthreads();
    const float4* wr = (const float4*)&W[k * 256 + h * 64];
    float acc = 0.f;
    #pragma unroll
    for (int q = 0; q < 16; q++) {
        float4 w4 = wr[q];
        acc = fmaf(w4.x, av[4 * q + 0], acc);
        acc = fmaf(w4.y, av[4 * q + 1], acc);
        acc = fmaf(w4.z, av[4 * q + 2], acc);
        acc = fmaf(w4.w, av[4 * q + 3], acc);
    }
    if (sel) g_wd[k * 4 + h] = acc; else g_ws[k * 4 + h] = acc;
}

// ---------------- init: out = dense_b + bias@dense_w (broadcast); denom=0 ----
__global__ void k_init(const float* __restrict__ bias,
                       const float* __restrict__ dw,
                       const float* __restrict__ db,
                       float* __restrict__ out, int N) {
    __shared__ float b2[64];
    int t = threadIdx.x;
    if (t < 64) {
        float acc = db[t];
        #pragma unroll 8
        for (int k = 0; k < 256; k++) acc = fmaf(bias[k], dw[k * 64 + t], acc);
        b2[t] = acc;
    }
    __syncthreads();
    int total = N * 64;
    for (int i = blockIdx.x * blockDim.x + t; i < total; i += gridDim.x * blockDim.x)
        out[i] = b2[i & 63];
    int td = N * 4;
    for (int i = blockIdx.x * blockDim.x + t; i < td; i += gridDim.x * blockDim.x)
        g_denom[i] = 0.f;
}

// ---------------- y = emb @ Wfold ([N,64] @ [64,256]) ----------------
__global__ void __launch_bounds__(256) k_proj(const float* __restrict__ emb, int N) {
    __shared__ float s_emb[8][64];
    int t = threadIdx.x;
    float w[64];
    #pragma unroll
    for (int k = 0; k < 64; k++) w[k] = g_wf[k * 256 + t];

    int base = blockIdx.x * 64;
    for (int ch = 0; ch < 8; ch++) {
        int r0 = base + ch * 8;
        for (int i = t; i < 512; i += 256) {
            int rr = i >> 6, cc = i & 63;
            int row = r0 + rr;
            s_emb[rr][cc] = (row < N) ? emb[row * 64 + cc] : 0.f;
        }
        __syncthreads();
        #pragma unroll
        for (int r = 0; r < 8; r++) {
            int row = r0 + r;
            if (row < N) {
                float acc = 0.f;
                const float4* ep = (const float4*)s_emb[r];
                #pragma unroll
                for (int q = 0; q < 16; q++) {
                    float4 e4 = ep[q];
                    acc = fmaf(e4.x, w[4 * q + 0], acc);
                    acc = fmaf(e4.y, w[4 * q + 1], acc);
                    acc = fmaf(e4.z, w[4 * q + 2], acc);
                    acc = fmaf(e4.w, w[4 * q + 3], acc);
                }
                g_y[row * 256 + t] = acc;
            }
        }
        __syncthreads();
    }
}

// ---------------- asrc/adst = emb @ ws / wd ----------------
// 256 threads / block: 32 nodes, 8 columns each (4 src + 4 dst).
__global__ void __launch_bounds__(256) k_att2(const float* __restrict__ emb, int N) {
    __shared__ float s_emb[32][65];
    __shared__ float s_w[64][8];
    int t = threadIdx.x;
    // load folded att weights
    for (int i = t; i < 512; i += 256) {
        int k = i >> 3, c = i & 7;
        s_w[k][c] = (c < 4) ? g_ws[k * 4 + c] : g_wd[k * 4 + (c - 4)];
    }
    int base = blockIdx.x * 32;
    for (int i = t; i < 2048; i += 256) {
        int rr = i >> 6, cc = i & 63;
        int row = base + rr;
        s_emb[rr][cc] = (row < N) ? emb[row * 64 + cc] : 0.f;
    }
    __syncthreads();
    int i = t >> 3, c8 = t & 7;
    int node = base + i;
    if (node < N) {
        float acc = 0.f;
        #pragma unroll
        for (int k = 0; k < 64; k++) acc = fmaf(s_emb[i][k], s_w[k][c8], acc);
        if (c8 < 4) g_asrc[node * 4 + c8] = acc;
        else        g_adst[node * 4 + (c8 - 4)] = acc;
    }
}

// ---------------- edge pass 1: ex = exp(leaky(alpha)); denom += ex ----------
__global__ void k_edge(const void* __restrict__ graph, int E, int ET) {
    int e = blockIdx.x * blockDim.x + threadIdx.x;
    if (e >= ET) return;
    int s, d;
    if (e < E) {
        if (g_is64) {
            const long long* g = (const long long*)graph;
            s = (int)g[e]; d = (int)g[E + e];
        } else {
            const int* g = (const int*)graph;
            s = g[e]; d = g[E + e];
        }
    } else {
        s = d = e - E;
    }
    g_sd[e] = make_int2(s, d);

    float4 as4 = *(const float4*)&g_asrc[s * 4];
    float4 ad4 = *(const float4*)&g_adst[d * 4];
    float a0 = as4.x + ad4.x, a1 = as4.y + ad4.y, a2 = as4.z + ad4.z, a3 = as4.w + ad4.w;
    a0 = (a0 > 0.f) ? a0 : 0.2f * a0;
    a1 = (a1 > 0.f) ? a1 : 0.2f * a1;
    a2 = (a2 > 0.f) ? a2 : 0.2f * a2;
    a3 = (a3 > 0.f) ? a3 : 0.2f * a3;
    float4 ex4 = make_float4(__expf(a0), __expf(a1), __expf(a2), __expf(a3));
    *(float4*)&g_ex[e * 4] = ex4;

    float* dp = &g_denom[d * 4];
    asm volatile("red.global.v4.f32.add [%0], {%1, %2, %3, %4};"
                 :: "l"(dp), "f"(ex4.x), "f"(ex4.y), "f"(ex4.z), "f"(ex4.w)
                 : "memory");
}

// ---------------- reciprocal of denom ----------------
__global__ void k_rdenom(int N4) {
    int i = blockIdx.x * blockDim.x + threadIdx.x;
    if (i < N4) g_denom[i] = 1.0f / (g_denom[i] + 1e-16f);
}

// ---------------- edge pass 2: out[dst] += sum_h coef_h * y[src,h,:] ---------
// 16 lanes/edge; leader loads metadata, broadcasts coef via shfl.
__global__ void __launch_bounds__(256) k_scatter(float* __restrict__ out, int ET) {
    int tid = blockIdx.x * blockDim.x + threadIdx.x;
    int e = tid >> 4;
    int sub = tid & 15;
    bool valid = (e < ET);
    int ec = valid ? e : (ET - 1);

    int s = 0, d = 0;
    float c0 = 0.f, c1 = 0.f, c2 = 0.f, c3 = 0.f;
    if (sub == 0) {
        int2 sd = g_sd[ec];
        s = sd.x; d = sd.y;
        float4 ex4 = *(const float4*)&g_ex[ec * 4];
        float4 rd  = *(const float4*)&g_denom[sd.y * 4];
        c0 = ex4.x * rd.x; c1 = ex4.y * rd.y; c2 = ex4.z * rd.z; c3 = ex4.w * rd.w;
    }
    unsigned m = 0xffffffffu;
    int src_lane = threadIdx.x & 16;   // leader lane of this half-warp
    s  = __shfl_sync(m, s,  src_lane);
    d  = __shfl_sync(m, d,  src_lane);
    c0 = __shfl_sync(m, c0, src_lane);
    c1 = __shfl_sync(m, c1, src_lane);
    c2 = __shfl_sync(m, c2, src_lane);
    c3 = __shfl_sync(m, c3, src_lane);

    const float4* yp = (const float4*)&g_y[(size_t)s * 256];
    float4 y0 = __ldg(&yp[0 * 16 + sub]);
    float4 y1 = __ldg(&yp[1 * 16 + sub]);
    float4 y2 = __ldg(&yp[2 * 16 + sub]);
    float4 y3 = __ldg(&yp[3 * 16 + sub]);

    float4 acc;
    acc.x = fmaf(c3, y3.x, fmaf(c2, y2.x, fmaf(c1, y1.x, c0 * y0.x)));
    acc.y = fmaf(c3, y3.y, fmaf(c2, y2.y, fmaf(c1, y1.y, c0 * y0.y)));
    acc.z = fmaf(c3, y3.z, fmaf(c2, y2.z, fmaf(c1, y1.z, c0 * y0.z)));
    acc.w = fmaf(c3, y3.w, fmaf(c2, y2.w, fmaf(c1, y1.w, c0 * y0.w)));

    if (valid) {
        float* op = out + (size_t)d * 64 + sub * 4;
        asm volatile("red.global.v4.f32.add [%0], {%1, %2, %3, %4};"
                     :: "l"(op), "f"(acc.x), "f"(acc.y), "f"(acc.z), "f"(acc.w)
                     : "memory");
    }
}

// ---------------- launch ----------------
extern "C" void kernel_launch(void* const* d_in, const int* in_sizes, int n_in,
                              void* d_out, int out_size) {
    const float* emb   = (const float*)d_in[0];
    const void*  graph = d_in[1];
    const float* W     = (const float*)d_in[2];
    const float* asr   = (const float*)d_in[3];
    const float* adt   = (const float*)d_in[4];
    const float* bias  = (const float*)d_in[5];
    const float* dw    = (const float*)d_in[6];
    const float* db    = (const float*)d_in[7];
    float* out = (float*)d_out;

    int N  = in_sizes[0] / 64;
    int E  = in_sizes[1] / 2;
    int ET = E + N;

    k_detect<<<1, 256>>>((const int*)graph);
    k_fold<<<256, 64>>>(W, dw);
    k_fatt<<<8, 64>>>(W, asr, adt);
    k_init<<<512, 256>>>(bias, dw, db, out, N);
    k_proj<<<(N + 63) / 64, 256>>>(emb, N);
    k_att2<<<(N + 31) / 32, 256>>>(emb, N);
    k_edge<<<(ET + 255) / 256, 256>>>(graph, E, ET);
    k_rdenom<<<(N * 4 + 255) / 256, 256>>>(N * 4);
    k_scatter<<<((size_t)ET * 16 + 255) / 256, 256>>>(out, ET);
}

// round 3
// speedup vs baseline: 1.6129x; 1.1053x over previous
#include <cuda_runtime.h>
#include <cuda_bf16.h>
#include <math.h>

#define NNODES 50000
#define NEDGES 800000
#define ETOT   (NEDGES + NNODES)

// ---------------- device scratch ----------------
__device__ float g_y[NNODES * 256];      // emb folded through W and dense_w: [N, H, 64]
__device__ float g_asrc[NNODES * 4];
__device__ float g_adst[NNODES * 4];
__device__ float g_denom[NNODES * 4];
__device__ float g_ex[ETOT * 4];
__device__ int2  g_sd[ETOT];
__device__ int   g_is64;
__device__ float g_wf[64 * 256];         // folded weights: emb -> y
__device__ float g_ws[64 * 4];           // emb -> a_src
__device__ float g_wd[64 * 4];           // emb -> a_dst
__device__ float g_b2[64];               // dense_b + bias @ dense_w

// ---------------- packed f32x2 helpers ----------------
__device__ __forceinline__ unsigned long long fma2(unsigned long long a,
                                                   unsigned long long b,
                                                   unsigned long long c) {
    unsigned long long d;
    asm("fma.rn.f32x2 %0, %1, %2, %3;" : "=l"(d) : "l"(a), "l"(b), "l"(c));
    return d;
}

// ---------------- prep: fold weights, att vectors, b2, dtype detect ---------
// grid 266 x 64 threads.
__global__ void __launch_bounds__(64) k_prep(const float* __restrict__ W,
                                             const float* __restrict__ dw,
                                             const float* __restrict__ asr,
                                             const float* __restrict__ adt,
                                             const float* __restrict__ bias,
                                             const float* __restrict__ db,
                                             const int* __restrict__ g32) {
    int b = blockIdx.x;
    int k = threadIdx.x;
    if (b < 256) {
        // Wfold[k, j] = sum_c W[k, h*64+c] * dw[(h*64+c), d],  j = h*64+d
        int j = b, h = j >> 6, d = j & 63;
        __shared__ float dcol[64];
        dcol[k] = dw[(h * 64 + k) * 64 + d];
        __syncthreads();
        const float4* wr = (const float4*)&W[k * 256 + h * 64];
        float acc = 0.f;
        #pragma unroll
        for (int q = 0; q < 16; q++) {
            float4 w4 = wr[q];
            acc = fmaf(w4.x, dcol[4 * q + 0], acc);
            acc = fmaf(w4.y, dcol[4 * q + 1], acc);
            acc = fmaf(w4.z, dcol[4 * q + 2], acc);
            acc = fmaf(w4.w, dcol[4 * q + 3], acc);
        }
        g_wf[k * 256 + j] = acc;
    } else if (b < 264) {
        // ws/wd[k, h] = sum_c W[k, h*64+c] * att[h, c]
        int bb = b - 256;
        int sel = bb >> 2, h = bb & 3;
        __shared__ float av[64];
        av[k] = sel ? adt[h * 64 + k] : asr[h * 64 + k];
        __syncthreads();
        const float4* wr = (const float4*)&W[k * 256 + h * 64];
        float acc = 0.f;
        #pragma unroll
        for (int q = 0; q < 16; q++) {
            float4 w4 = wr[q];
            acc = fmaf(w4.x, av[4 * q + 0], acc);
            acc = fmaf(w4.y, av[4 * q + 1], acc);
            acc = fmaf(w4.z, av[4 * q + 2], acc);
            acc = fmaf(w4.w, av[4 * q + 3], acc);
        }
        if (sel) g_wd[k * 4 + h] = acc; else g_ws[k * 4 + h] = acc;
    } else if (b == 264) {
        // b2 = dense_b + bias @ dense_w
        float acc = db[k];
        #pragma unroll 8
        for (int c = 0; c < 256; c++) acc = fmaf(bias[c], dw[c * 64 + k], acc);
        g_b2[k] = acc;
    } else {
        // dtype detect: if int64 little-endian with small values, odd words are 0
        __shared__ int any_nonzero;
        if (k == 0) any_nonzero = 0;
        __syncthreads();
        int nz = 0;
        #pragma unroll
        for (int r = 0; r < 4; r++) nz |= g32[2 * (k + 64 * r) + 1];
        if (nz != 0) any_nonzero = 1;
        __syncthreads();
        if (k == 0) g_is64 = (any_nonzero == 0) ? 1 : 0;
    }
}

// ---------------- phase 1 (fused): per block of 64 nodes ---------------------
//  - load emb tile (transposed, padded stride 68 for pair-packed reads)
//  - init out rows with b2, zero denom
//  - proj: y = emb @ Wfold via packed f32x2 (thread = output column)
//  - att:  asrc/adst = emb @ ws/wd
__global__ void __launch_bounds__(256, 1) k_phase1(const float* __restrict__ emb,
                                                   float* __restrict__ out, int N) {
    __shared__ __align__(16) float s[64 * 68];   // s[k*68 + row_offset]
    __shared__ float s_w[64 * 8];                // [k][0..3]=ws, [4..7]=wd
    __shared__ float s_b2[64];
    int t = threadIdx.x;
    int base = blockIdx.x * 64;

    // folded proj weights -> registers, duplicated for f32x2
    unsigned long long w2[64];
    #pragma unroll
    for (int k = 0; k < 64; k++) {
        float w = g_wf[k * 256 + t];
        asm("mov.b64 %0, {%1, %1};" : "=l"(w2[k]) : "f"(w));
    }
    // att weights + b2 -> smem
    for (int i = t; i < 512; i += 256) {
        int k = i >> 3, c = i & 7;
        s_w[i] = (c < 4) ? g_ws[k * 4 + c] : g_wd[k * 4 + (c - 4)];
    }
    if (t < 64) s_b2[t] = g_b2[t];

    // emb tile, transposed: s[k*68 + ro] = emb[base+ro][k]
    #pragma unroll
    for (int j = 0; j < 16; j++) {
        int g = j * 256 + t;
        int ro = g >> 6, k = g & 63;
        int row = base + ro;
        s[k * 68 + ro] = (row < N) ? emb[row * 64 + k] : 0.f;
    }
    __syncthreads();

    // ---- init: out rows = b2, denom = 0 ----
    #pragma unroll
    for (int j = 0; j < 16; j++) {
        int g = j * 256 + t;
        int ro = g >> 6, c = g & 63;
        int row = base + ro;
        if (row < N) out[row * 64 + c] = s_b2[c];
    }
    {
        int node = base + (t >> 2);
        if (node < N) g_denom[node * 4 + (t & 3)] = 0.f;
    }

    // ---- proj: thread t = output column, 4 chunks of 16 rows (8 pairs) ----
    for (int c = 0; c < 4; c++) {
        unsigned long long acc[8];
        #pragma unroll
        for (int p = 0; p < 8; p++) acc[p] = 0ull;
        #pragma unroll
        for (int k = 0; k < 64; k++) {
            const ulonglong2* sp = (const ulonglong2*)&s[k * 68 + 16 * c];
            #pragma unroll
            for (int q = 0; q < 4; q++) {
                ulonglong2 v = sp[q];
                acc[2 * q]     = fma2(v.x, w2[k], acc[2 * q]);
                acc[2 * q + 1] = fma2(v.y, w2[k], acc[2 * q + 1]);
            }
        }
        #pragma unroll
        for (int p = 0; p < 8; p++) {
            float lo, hi;
            asm("mov.b64 {%0, %1}, %2;" : "=f"(lo), "=f"(hi) : "l"(acc[p]));
            int r0 = base + 16 * c + 2 * p;
            if (r0 < N)     g_y[(size_t)r0 * 256 + t] = lo;
            if (r0 + 1 < N) g_y[(size_t)(r0 + 1) * 256 + t] = hi;
        }
    }

    // ---- att logits: thread -> (node i = t>>2, head hh = t&3) ----
    {
        int i = t >> 2, hh = t & 3;
        float as = 0.f, ad = 0.f;
        #pragma unroll 8
        for (int k = 0; k < 64; k++) {
            float e = s[k * 68 + i];
            as = fmaf(e, s_w[k * 8 + hh], as);
            ad = fmaf(e, s_w[k * 8 + 4 + hh], ad);
        }
        int node = base + i;
        if (node < N) {
            g_asrc[node * 4 + hh] = as;
            g_adst[node * 4 + hh] = ad;
        }
    }
}

// ---------------- edge pass 1: ex = exp(leaky(alpha)); denom += ex ----------
__global__ void k_edge(const void* __restrict__ graph, int E, int ET) {
    int e = blockIdx.x * blockDim.x + threadIdx.x;
    if (e >= ET) return;
    int s, d;
    if (e < E) {
        if (g_is64) {
            const long long* g = (const long long*)graph;
            s = (int)g[e]; d = (int)g[E + e];
        } else {
            const int* g = (const int*)graph;
            s = g[e]; d = g[E + e];
        }
    } else {
        s = d = e - E;   // self loop
    }
    g_sd[e] = make_int2(s, d);

    float4 as4 = *(const float4*)&g_asrc[s * 4];
    float4 ad4 = *(const float4*)&g_adst[d * 4];
    float a0 = as4.x + ad4.x, a1 = as4.y + ad4.y, a2 = as4.z + ad4.z, a3 = as4.w + ad4.w;
    a0 = (a0 > 0.f) ? a0 : 0.2f * a0;
    a1 = (a1 > 0.f) ? a1 : 0.2f * a1;
    a2 = (a2 > 0.f) ? a2 : 0.2f * a2;
    a3 = (a3 > 0.f) ? a3 : 0.2f * a3;
    float4 ex4 = make_float4(__expf(a0), __expf(a1), __expf(a2), __expf(a3));
    *(float4*)&g_ex[e * 4] = ex4;

    float* dp = &g_denom[d * 4];
    asm volatile("red.global.v4.f32.add [%0], {%1, %2, %3, %4};"
                 :: "l"(dp), "f"(ex4.x), "f"(ex4.y), "f"(ex4.z), "f"(ex4.w)
                 : "memory");
}

// ---------------- edge pass 2: out[dst] += sum_h coef_h * y[src,h,:] ---------
__global__ void __launch_bounds__(256) k_scatter(float* __restrict__ out, int ET) {
    int tid = blockIdx.x * blockDim.x + threadIdx.x;
    int e = tid >> 4;
    int sub = tid & 15;
    bool valid = (e < ET);
    int ec = valid ? e : (ET - 1);

    int s = 0, d = 0;
    float c0 = 0.f, c1 = 0.f, c2 = 0.f, c3 = 0.f;
    if (sub == 0) {
        int2 sd = g_sd[ec];
        s = sd.x; d = sd.y;
        float4 ex4 = *(const float4*)&g_ex[ec * 4];
        float4 dn  = *(const float4*)&g_denom[sd.y * 4];
        c0 = __fdividef(ex4.x, dn.x + 1e-16f);
        c1 = __fdividef(ex4.y, dn.y + 1e-16f);
        c2 = __fdividef(ex4.z, dn.z + 1e-16f);
        c3 = __fdividef(ex4.w, dn.w + 1e-16f);
    }
    unsigned m = 0xffffffffu;
    int src_lane = threadIdx.x & 16;   // leader of this half-warp
    s  = __shfl_sync(m, s,  src_lane);
    d  = __shfl_sync(m, d,  src_lane);
    c0 = __shfl_sync(m, c0, src_lane);
    c1 = __shfl_sync(m, c1, src_lane);
    c2 = __shfl_sync(m, c2, src_lane);
    c3 = __shfl_sync(m, c3, src_lane);

    const float4* yp = (const float4*)&g_y[(size_t)s * 256];
    float4 y0 = __ldg(&yp[0 * 16 + sub]);
    float4 y1 = __ldg(&yp[1 * 16 + sub]);
    float4 y2 = __ldg(&yp[2 * 16 + sub]);
    float4 y3 = __ldg(&yp[3 * 16 + sub]);

    float4 acc;
    acc.x = fmaf(c3, y3.x, fmaf(c2, y2.x, fmaf(c1, y1.x, c0 * y0.x)));
    acc.y = fmaf(c3, y3.y, fmaf(c2, y2.y, fmaf(c1, y1.y, c0 * y0.y)));
    acc.z = fmaf(c3, y3.z, fmaf(c2, y2.z, fmaf(c1, y1.z, c0 * y0.z)));
    acc.w = fmaf(c3, y3.w, fmaf(c2, y2.w, fmaf(c1, y1.w, c0 * y0.w)));

    if (valid) {
        float* op = out + (size_t)d * 64 + sub * 4;
        asm volatile("red.global.v4.f32.add [%0], {%1, %2, %3, %4};"
                     :: "l"(op), "f"(acc.x), "f"(acc.y), "f"(acc.z), "f"(acc.w)
                     : "memory");
    }
}

// ---------------- launch ----------------
extern "C" void kernel_launch(void* const* d_in, const int* in_sizes, int n_in,
                              void* d_out, int out_size) {
    const float* emb   = (const float*)d_in[0];
    const void*  graph = d_in[1];
    const float* W     = (const float*)d_in[2];
    const float* asr   = (const float*)d_in[3];
    const float* adt   = (const float*)d_in[4];
    const float* bias  = (const float*)d_in[5];
    const float* dw    = (const float*)d_in[6];
    const float* db    = (const float*)d_in[7];
    float* out = (float*)d_out;

    int N  = in_sizes[0] / 64;
    int E  = in_sizes[1] / 2;
    int ET = E + N;

    k_prep<<<266, 64>>>(W, dw, asr, adt, bias, db, (const int*)graph);
    k_phase1<<<(N + 63) / 64, 256>>>(emb, out, N);
    k_edge<<<(ET + 255) / 256, 256>>>(graph, E, ET);
    k_scatter<<<((size_t)ET * 16 + 255) / 256, 256>>>(out, ET);
}

// round 4
// speedup vs baseline: 2.5351x; 1.5718x over previous
#include <cuda_runtime.h>
#include <cuda_bf16.h>
#include <cuda_fp16.h>
#include <math.h>

#define NNODES 50000
#define NEDGES 800000
#define ETOT   (NEDGES + NNODES)

// ---------------- device scratch ----------------
__device__ __half g_y2[NNODES * 256];    // folded features, fp16, scatter-packed:
                                         // y2[n][16*sub + 4*h + i] = y[n][h][4*sub+i]
__device__ float  g_asrc[NNODES * 4];
__device__ float  g_adst[NNODES * 4];
__device__ float  g_denom[NNODES * 4];
__device__ float  g_ex[ETOT * 4];
__device__ int2   g_sd[ETOT];
__device__ int    g_is64;
__device__ __half g_wfh[256 * 64];       // folded weights, fp16, TRANSPOSED: [n][k]
__device__ float  g_ws[64 * 4];          // emb -> a_src
__device__ float  g_wd[64 * 4];          // emb -> a_dst
__device__ float  g_b2[64];              // dense_b + bias @ dense_w

// ---------------- prep: folds + b2 + dtype detect ----------------
__global__ void __launch_bounds__(64) k_prep(const float* __restrict__ W,
                                             const float* __restrict__ dw,
                                             const float* __restrict__ asr,
                                             const float* __restrict__ adt,
                                             const float* __restrict__ bias,
                                             const float* __restrict__ db,
                                             const int* __restrict__ g32) {
    int b = blockIdx.x;
    int k = threadIdx.x;
    if (b < 256) {
        // Wfold[k, j] = sum_c W[k, h*64+c] * dw[(h*64+c), d],  j = h*64+d
        int j = b, h = j >> 6, d = j & 63;
        __shared__ float dcol[64];
        dcol[k] = dw[(h * 64 + k) * 64 + d];
        __syncthreads();
        const float4* wr = (const float4*)&W[k * 256 + h * 64];
        float acc = 0.f;
        #pragma unroll
        for (int q = 0; q < 16; q++) {
            float4 w4 = wr[q];
            acc = fmaf(w4.x, dcol[4 * q + 0], acc);
            acc = fmaf(w4.y, dcol[4 * q + 1], acc);
            acc = fmaf(w4.z, dcol[4 * q + 2], acc);
            acc = fmaf(w4.w, dcol[4 * q + 3], acc);
        }
        g_wfh[j * 64 + k] = __float2half_rn(acc);   // transposed fp16
    } else if (b < 264) {
        int bb = b - 256;
        int sel = bb >> 2, h = bb & 3;
        __shared__ float av[64];
        av[k] = sel ? adt[h * 64 + k] : asr[h * 64 + k];
        __syncthreads();
        const float4* wr = (const float4*)&W[k * 256 + h * 64];
        float acc = 0.f;
        #pragma unroll
        for (int q = 0; q < 16; q++) {
            float4 w4 = wr[q];
            acc = fmaf(w4.x, av[4 * q + 0], acc);
            acc = fmaf(w4.y, av[4 * q + 1], acc);
            acc = fmaf(w4.z, av[4 * q + 2], acc);
            acc = fmaf(w4.w, av[4 * q + 3], acc);
        }
        if (sel) g_wd[k * 4 + h] = acc; else g_ws[k * 4 + h] = acc;
    } else if (b == 264) {
        float acc = db[k];
        #pragma unroll 8
        for (int c = 0; c < 256; c++) acc = fmaf(bias[c], dw[c * 64 + k], acc);
        g_b2[k] = acc;
    } else {
        __shared__ int any_nonzero;
        if (k == 0) any_nonzero = 0;
        __syncthreads();
        int nz = 0;
        #pragma unroll
        for (int r = 0; r < 4; r++) nz |= g32[2 * (k + 64 * r) + 1];
        if (nz != 0) any_nonzero = 1;
        __syncthreads();
        if (k == 0) g_is64 = (any_nonzero == 0) ? 1 : 0;
    }
}

// ---------------- phase 1 (fused, HMMA): block = 64 nodes ----------------
__global__ void __launch_bounds__(256) k_phase1(const float* __restrict__ emb,
                                                float* __restrict__ out, int N) {
    __shared__ float  sf[64 * 68];     // fp32 emb tile [row][k], stride 68
    __shared__ __half ah[64 * 72];     // fp16 emb tile [row][k], stride 72
    __shared__ float  s_w[64 * 8];     // att folds: [k][0..3]=ws, [4..7]=wd
    __shared__ float  s_b2[64];
    int t = threadIdx.x;
    int base = blockIdx.x * 64;

    for (int i = t; i < 512; i += 256) {
        int k = i >> 3, c = i & 7;
        s_w[i] = (c < 4) ? g_ws[k * 4 + c] : g_wd[k * 4 + (c - 4)];
    }
    if (t < 64) s_b2[t] = g_b2[t];

    // load fp32 emb tile (coalesced), then fp16 copy
    #pragma unroll
    for (int j = 0; j < 16; j++) {
        int g = j * 256 + t;
        int ro = g >> 6, k = g & 63;
        int row = base + ro;
        float v = (row < N) ? emb[row * 64 + k] : 0.f;
        sf[ro * 68 + k] = v;
        ah[ro * 72 + k] = __float2half_rn(v);
    }
    __syncthreads();

    // ---- init: out rows = b2 (float4), denom = 0 ----
    {
        int ro = t >> 2, q = t & 3;            // 64 rows x 4 float4-chunks
        int row = base + ro;
        const float4* b4 = (const float4*)s_b2;
        if (row < N) {
            float4* o4 = (float4*)&out[row * 64];
            #pragma unroll
            for (int j = 0; j < 4; j++) o4[4 * j + q] = b4[4 * j + q];
        }
        int node = base + ro;
        if (node < N) g_denom[node * 4 + q] = 0.f;
    }

    // ---- proj via mma.sync m16n8k16: warp w -> cols 32w..32w+31, all 64 rows
    {
        int w = t >> 5, lane = t & 31;
        int gid = lane >> 2, tig = lane & 3;

        // B fragments (register resident): 4 n8-tiles x 4 k-steps x 2 regs
        unsigned bfr[4][4][2];
        #pragma unroll
        for (int tn = 0; tn < 4; tn++) {
            int n = 32 * w + 8 * tn + gid;
            #pragma unroll
            for (int ks = 0; ks < 4; ks++) {
                bfr[tn][ks][0] = *(const unsigned*)&g_wfh[n * 64 + 16 * ks + 2 * tig];
                bfr[tn][ks][1] = *(const unsigned*)&g_wfh[n * 64 + 16 * ks + 2 * tig + 8];
            }
        }

        float acc[4][4][4];
        #pragma unroll
        for (int mg = 0; mg < 4; mg++)
            #pragma unroll
            for (int tn = 0; tn < 4; tn++)
                #pragma unroll
                for (int q = 0; q < 4; q++) acc[mg][tn][q] = 0.f;

        #pragma unroll
        for (int mg = 0; mg < 4; mg++) {
            int r0 = 16 * mg + gid;
            #pragma unroll
            for (int ks = 0; ks < 4; ks++) {
                unsigned a0 = *(const unsigned*)&ah[r0 * 72 + 16 * ks + 2 * tig];
                unsigned a1 = *(const unsigned*)&ah[(r0 + 8) * 72 + 16 * ks + 2 * tig];
                unsigned a2 = *(const unsigned*)&ah[r0 * 72 + 16 * ks + 2 * tig + 8];
                unsigned a3 = *(const unsigned*)&ah[(r0 + 8) * 72 + 16 * ks + 2 * tig + 8];
                #pragma unroll
                for (int tn = 0; tn < 4; tn++) {
                    asm("mma.sync.aligned.m16n8k16.row.col.f32.f16.f16.f32 "
                        "{%0,%1,%2,%3}, {%4,%5,%6,%7}, {%8,%9}, {%0,%1,%2,%3};"
                        : "+f"(acc[mg][tn][0]), "+f"(acc[mg][tn][1]),
                          "+f"(acc[mg][tn][2]), "+f"(acc[mg][tn][3])
                        : "r"(a0), "r"(a1), "r"(a2), "r"(a3),
                          "r"(bfr[tn][ks][0]), "r"(bfr[tn][ks][1]));
                }
            }
        }

        // write y2 fp16 in scatter-packed layout
        #pragma unroll
        for (int mg = 0; mg < 4; mg++) {
            #pragma unroll
            for (int tn = 0; tn < 4; tn++) {
                int j = 32 * w + 8 * tn + 2 * tig;     // even col
                int h = j >> 6, d = j & 63;
                int idx = 16 * (d >> 2) + 4 * h + (d & 3);
                int r = base + 16 * mg + gid;
                if (r < N) {
                    __half2 v = __floats2half2_rn(acc[mg][tn][0], acc[mg][tn][1]);
                    *(__half2*)&g_y2[(size_t)r * 256 + idx] = v;
                }
                if (r + 8 < N) {
                    __half2 v = __floats2half2_rn(acc[mg][tn][2], acc[mg][tn][3]);
                    *(__half2*)&g_y2[(size_t)(r + 8) * 256 + idx] = v;
                }
            }
        }
    }

    // ---- att logits (fp32): thread -> (node i = t>>2, head hh = t&3) ----
    {
        int i = t >> 2, hh = t & 3;
        float as = 0.f, ad = 0.f;
        #pragma unroll 8
        for (int k = 0; k < 64; k++) {
            float e = sf[i * 68 + k];
            as = fmaf(e, s_w[k * 8 + hh], as);
            ad = fmaf(e, s_w[k * 8 + 4 + hh], ad);
        }
        int node = base + i;
        if (node < N) {
            g_asrc[node * 4 + hh] = as;
            g_adst[node * 4 + hh] = ad;
        }
    }
}

// ---------------- edge pass 1: ex = exp(leaky(alpha)); denom += ex ----------
__global__ void k_edge(const void* __restrict__ graph, int E, int ET) {
    int e = blockIdx.x * blockDim.x + threadIdx.x;
    if (e >= ET) return;
    int s, d;
    if (e < E) {
        if (g_is64) {
            const long long* g = (const long long*)graph;
            s = (int)g[e]; d = (int)g[E + e];
        } else {
            const int* g = (const int*)graph;
            s = g[e]; d = g[E + e];
        }
    } else {
        s = d = e - E;   // self loop
    }
    g_sd[e] = make_int2(s, d);

    float4 as4 = *(const float4*)&g_asrc[s * 4];
    float4 ad4 = *(const float4*)&g_adst[d * 4];
    float a0 = as4.x + ad4.x, a1 = as4.y + ad4.y, a2 = as4.z + ad4.z, a3 = as4.w + ad4.w;
    a0 = (a0 > 0.f) ? a0 : 0.2f * a0;
    a1 = (a1 > 0.f) ? a1 : 0.2f * a1;
    a2 = (a2 > 0.f) ? a2 : 0.2f * a2;
    a3 = (a3 > 0.f) ? a3 : 0.2f * a3;
    float4 ex4 = make_float4(__expf(a0), __expf(a1), __expf(a2), __expf(a3));
    *(float4*)&g_ex[e * 4] = ex4;

    float* dp = &g_denom[d * 4];
    asm volatile("red.global.v4.f32.add [%0], {%1, %2, %3, %4};"
                 :: "l"(dp), "f"(ex4.x), "f"(ex4.y), "f"(ex4.z), "f"(ex4.w)
                 : "memory");
}

// ---------------- edge pass 2: out[dst] += sum_h coef_h * y[src,h,:] ---------
__global__ void __launch_bounds__(256) k_scatter(float* __restrict__ out, int ET) {
    int tid = blockIdx.x * blockDim.x + threadIdx.x;
    int e = tid >> 4;
    int sub = tid & 15;
    bool valid = (e < ET);
    int ec = valid ? e : (ET - 1);

    int s = 0, d = 0;
    float c0 = 0.f, c1 = 0.f, c2 = 0.f, c3 = 0.f;
    if (sub == 0) {
        int2 sd = g_sd[ec];
        s = sd.x; d = sd.y;
        float4 ex4 = *(const float4*)&g_ex[ec * 4];
        float4 dn  = *(const float4*)&g_denom[sd.y * 4];
        c0 = __fdividef(ex4.x, dn.x + 1e-16f);
        c1 = __fdividef(ex4.y, dn.y + 1e-16f);
        c2 = __fdividef(ex4.z, dn.z + 1e-16f);
        c3 = __fdividef(ex4.w, dn.w + 1e-16f);
    }
    unsigned m = 0xffffffffu;
    int src_lane = threadIdx.x & 16;
    s  = __shfl_sync(m, s,  src_lane);
    d  = __shfl_sync(m, d,  src_lane);
    c0 = __shfl_sync(m, c0, src_lane);
    c1 = __shfl_sync(m, c1, src_lane);
    c2 = __shfl_sync(m, c2, src_lane);
    c3 = __shfl_sync(m, c3, src_lane);

    // lane sub: 32B contiguous = all 4 heads x 4 dims for dims [4sub..4sub+3]
    const uint4* yp = (const uint4*)&g_y2[(size_t)s * 256];
    uint4 ua = __ldg(&yp[2 * sub]);       // h0: (i0,i1)(i2,i3), h1: (i0,i1)(i2,i3)
    uint4 ub = __ldg(&yp[2 * sub + 1]);   // h2, h3

    float2 h0a = __half22float2(*(__half2*)&ua.x);
    float2 h0b = __half22float2(*(__half2*)&ua.y);
    float2 h1a = __half22float2(*(__half2*)&ua.z);
    float2 h1b = __half22float2(*(__half2*)&ua.w);
    float2 h2a = __half22float2(*(__half2*)&ub.x);
    float2 h2b = __half22float2(*(__half2*)&ub.y);
    float2 h3a = __half22float2(*(__half2*)&ub.z);
    float2 h3b = __half22float2(*(__half2*)&ub.w);

    float4 acc;
    acc.x = fmaf(c3, h3a.x, fmaf(c2, h2a.x, fmaf(c1, h1a.x, c0 * h0a.x)));
    acc.y = fmaf(c3, h3a.y, fmaf(c2, h2a.y, fmaf(c1, h1a.y, c0 * h0a.y)));
    acc.z = fmaf(c3, h3b.x, fmaf(c2, h2b.x, fmaf(c1, h1b.x, c0 * h0b.x)));
    acc.w = fmaf(c3, h3b.y, fmaf(c2, h2b.y, fmaf(c1, h1b.y, c0 * h0b.y)));

    if (valid) {
        float* op = out + (size_t)d * 64 + sub * 4;
        asm volatile("red.global.v4.f32.add [%0], {%1, %2, %3, %4};"
                     :: "l"(op), "f"(acc.x), "f"(acc.y), "f"(acc.z), "f"(acc.w)
                     : "memory");
    }
}

// ---------------- launch ----------------
extern "C" void kernel_launch(void* const* d_in, const int* in_sizes, int n_in,
                              void* d_out, int out_size) {
    const float* emb   = (const float*)d_in[0];
    const void*  graph = d_in[1];
    const float* W     = (const float*)d_in[2];
    const float* asr   = (const float*)d_in[3];
    const float* adt   = (const float*)d_in[4];
    const float* bias  = (const float*)d_in[5];
    const float* dw    = (const float*)d_in[6];
    const float* db    = (const float*)d_in[7];
    float* out = (float*)d_out;

    int N  = in_sizes[0] / 64;
    int E  = in_sizes[1] / 2;
    int ET = E + N;

    k_prep<<<266, 64>>>(W, dw, asr, adt, bias, db, (const int*)graph);
    k_phase1<<<(N + 63) / 64, 256>>>(emb, out, N);
    k_edge<<<(ET + 255) / 256, 256>>>(graph, E, ET);
    k_scatter<<<((size_t)ET * 16 + 255) / 256, 256>>>(out, ET);
}